// round 10
// baseline (speedup 1.0000x reference)
#include <cuda_runtime.h>
#include <cuda_bf16.h>
#include <cstdint>

#define N_ROWS 4096
#define DIM    512
#define BK 128
#define K_HALF 2048
#define K_ITERS (K_HALF / BK)            // 16
#define ROW_BYTES 256                    // BK=128 bf16
#define TILE_HALF (64 * ROW_BYTES)       // 16KB per operand tile
#define STAGE_BYTES (2 * TILE_HALF)      // 32KB
#define STAGES 3
#define SMEM_GRAM (STAGES * STAGE_BYTES + 1024)   // ~97KB
#define SMEM_NT   (32 * 513 * 4)

#define NCLUSTERS 352

// Scratch: transposed normalized bf16: [mat][d][k], k contiguous
static __device__ __nv_bfloat16 g_normT[4][DIM][N_ROWS];
static __device__ float g_part[NCLUSTERS];
static __device__ unsigned int g_ctr;    // zero-init; self-reset by last block

__constant__ int   c_symmat[4] = {3, 0, 1, 2};
__constant__ float c_symw[4]   = {3.f, 1.f, 1.f, 1.f};
__constant__ int   c_ty10[10]  = {0,0,0,0,1,1,1,2,2,3};
__constant__ int   c_tx10[10]  = {0,1,2,3,1,2,3,2,3,3};

// ---------------------------------------------------------------------------
__device__ __forceinline__ uint32_t s2u(const void* p) {
    uint32_t a;
    asm("{ .reg .u64 t; cvta.to.shared.u64 t, %1; cvt.u32.u64 %0, t; }"
        : "=r"(a) : "l"(p));
    return a;
}
__device__ __forceinline__ void cpasync16(uint32_t dst, const void* src) {
    asm volatile("cp.async.cg.shared.global [%0], [%1], 16;" :: "r"(dst), "l"(src) : "memory");
}
__device__ __forceinline__ void ldsm4(uint32_t& r0, uint32_t& r1, uint32_t& r2,
                                      uint32_t& r3, uint32_t addr) {
    asm volatile("ldmatrix.sync.aligned.m8n8.x4.shared.b16 {%0,%1,%2,%3}, [%4];"
                 : "=r"(r0), "=r"(r1), "=r"(r2), "=r"(r3) : "r"(addr));
}
__device__ __forceinline__ void mma16816(float* c, const uint32_t* a, const uint32_t* b) {
    asm volatile(
        "mma.sync.aligned.m16n8k16.row.col.f32.bf16.bf16.f32 "
        "{%0,%1,%2,%3}, {%4,%5,%6,%7}, {%8,%9}, {%0,%1,%2,%3};"
        : "+f"(c[0]), "+f"(c[1]), "+f"(c[2]), "+f"(c[3])
        : "r"(a[0]), "r"(a[1]), "r"(a[2]), "r"(a[3]), "r"(b[0]), "r"(b[1]));
}

// ---------------------------------------------------------------------------
// K1: fused per-row L2 norm + normalize + transpose + bf16 cast.
// ---------------------------------------------------------------------------
__global__ __launch_bounds__(256) void norm_transpose_kernel(
    const float* __restrict__ in0, const float* __restrict__ in1,
    const float* __restrict__ in2, const float* __restrict__ in3)
{
    extern __shared__ float tl[];        // [32][513]
    __shared__ float sinv[32];
    const int mat = blockIdx.y;
    const int kc  = blockIdx.x;          // 0..127
    const float* src = (mat == 0) ? in0 : (mat == 1) ? in1 : (mat == 2) ? in2 : in3;
    const int t = threadIdx.x, lane = t & 31, wid = t >> 5;

    const float4* src4 = (const float4*)(src + (size_t)kc * 32 * DIM);
#pragma unroll
    for (int i = 0; i < 16; i++) {
        int idx = t + i * 256;
        int r = idx >> 7, c4 = idx & 127;
        float4 v = src4[idx];
        float* d = &tl[r * 513 + c4 * 4];
        d[0] = v.x; d[1] = v.y; d[2] = v.z; d[3] = v.w;
    }
    __syncthreads();

#pragma unroll
    for (int rr = 0; rr < 4; rr++) {
        int r = wid * 4 + rr;
        float ss = 0.f;
#pragma unroll
        for (int j = 0; j < 16; j++) {
            float v = tl[r * 513 + lane + j * 32];
            ss += v * v;
        }
#pragma unroll
        for (int o = 16; o > 0; o >>= 1) ss += __shfl_xor_sync(0xffffffffu, ss, o);
        if (lane == 0) sinv[r] = rsqrtf(fmaxf(ss, 1e-24f));
    }
    __syncthreads();

#pragma unroll
    for (int h = 0; h < 2; h++) {
        int d = t + h * 256;
        union { uint32_t u[16]; uint4 v[4]; } pk;
#pragma unroll
        for (int k2 = 0; k2 < 16; k2++) {
            float f0 = tl[(2 * k2    ) * 513 + d] * sinv[2 * k2];
            float f1 = tl[(2 * k2 + 1) * 513 + d] * sinv[2 * k2 + 1];
            __nv_bfloat162 b2 = __floats2bfloat162_rn(f0, f1);
            pk.u[k2] = *(uint32_t*)&b2;
        }
        uint4* dst = (uint4*)&g_normT[mat][d][kc * 32];
#pragma unroll
        for (int q = 0; q < 4; q++) dst[q] = pk.v[q];
    }
}

// ---------------------------------------------------------------------------
// K2: 704 CTAs in 352 cluster pairs. Each CTA: 64x64 x K=2048 (its k-half).
// 128 threads = 4 warps; warp w does k16-chunks {2w, 2w+1} of each BK=128 slab.
// Rank1 ships its partial C to rank0 via DSMEM; rank0 adds, squares, reduces.
// ---------------------------------------------------------------------------
__global__ __launch_bounds__(128, 2) __cluster_dims__(2, 1, 1)
void gram_kernel(float* __restrict__ out)
{
    extern __shared__ char dyn[];
    __shared__ float red[4];
    __shared__ float fr[128];
    __shared__ int s_last;

    // ---- decode: cluster -> quadrant unit, rank -> k-half
    const int cid  = blockIdx.x >> 1;
    const int rank = blockIdx.x & 1;
    int matL, matR, m0, n0; float w;
    if (cid < 160) {
        int p = cid / 40, rem = cid % 40;
        int t = rem >> 2, quad = rem & 3;
        matL = matR = c_symmat[p];
        int ty = c_ty10[t], tx = c_tx10[t];
        m0 = ty * 128 + (quad >> 1) * 64;
        n0 = tx * 128 + (quad & 1) * 64;
        w = c_symw[p] * ((ty == tx) ? 1.f : 2.f);
    } else {
        int q = cid - 160;
        matL = 3; matR = q / 64;
        int rem = q % 64;
        int t = rem >> 2, quad = rem & 3;
        m0 = (t >> 2) * 128 + (quad >> 1) * 64;
        n0 = (t & 3) * 128 + (quad & 1) * 64;
        w = -2.f;
    }
    const char* __restrict__ Ab = (const char*)&g_normT[matL][0][0];
    const char* __restrict__ Bb = (const char*)&g_normT[matR][0][0];
    const uint32_t kbyte0 = (uint32_t)rank * (K_HALF * 2);   // byte offset of k-half

    const int tid  = threadIdx.x;
    const int lane = tid & 31;
    const int wid  = tid >> 5;
    const uint32_t dyn_sa = s2u(dyn);
    const uint32_t dynb = (dyn_sa + 1023) & ~1023u;
    // generic pointer matching shared address dynb (writer/reader MUST agree)
    char* dynp = dyn + (dynb - dyn_sa);

    // ---- cp.async: 2048 16B chunks per stage (A 64 rows, B 64 rows), 16/thread
    auto issue_loads = [&](int it) {
        uint32_t sbase = dynb + (uint32_t)(it % STAGES) * STAGE_BYTES;
#pragma unroll
        for (int q = 0; q < 16; q++) {
            int c   = tid + q * 128;           // 0..2047
            int isB = c >> 10;
            int row = (c & 1023) >> 4;         // 0..63
            int q16 = c & 15;
            uint32_t sw = (uint32_t)row * ROW_BYTES + (uint32_t)((q16 ^ (row & 7)) << 4);
            const char* g = (isB ? Bb : Ab)
                          + ((size_t)((isB ? n0 : m0) + row) << 13)   // d-row * 8192B
                          + kbyte0 + (size_t)it * ROW_BYTES + q16 * 16;
            cpasync16(sbase + (isB ? TILE_HALF : 0) + sw, g);
        }
        asm volatile("cp.async.commit_group;" ::: "memory");
    };

    // ---- ldmatrix addressing
    uint32_t a_off[4], a_xor[4];
#pragma unroll
    for (int i = 0; i < 4; i++) {
        int row = i * 16 + (lane & 15);
        a_off[i] = (uint32_t)row * ROW_BYTES;
        a_xor[i] = (uint32_t)(row & 7);
    }
    const uint32_t a_hi = (uint32_t)(lane >> 4);
    uint32_t b_off[4], b_xor[4];
#pragma unroll
    for (int g = 0; g < 4; g++) {
        int row = g * 16 + ((lane >> 4) & 1) * 8 + (lane & 7);
        b_off[g] = (uint32_t)row * ROW_BYTES;
        b_xor[g] = (uint32_t)(row & 7);
    }
    const uint32_t b_hi = (uint32_t)((lane >> 3) & 1);

    float acc[4][8][4];
#pragma unroll
    for (int i = 0; i < 4; i++)
#pragma unroll
        for (int j = 0; j < 8; j++)
#pragma unroll
            for (int r = 0; r < 4; r++) acc[i][j][r] = 0.f;

    issue_loads(0);
    issue_loads(1);

    for (int it = 0; it < K_ITERS; ++it) {
        if (it < K_ITERS - 1)
            asm volatile("cp.async.wait_group 1;" ::: "memory");
        else
            asm volatile("cp.async.wait_group 0;" ::: "memory");
        __syncthreads();

        const int nx = it + 2;
        if (nx < K_ITERS) issue_loads(nx);

        const uint32_t sA = dynb + (uint32_t)(it % STAGES) * STAGE_BYTES;
        const uint32_t sB = sA + TILE_HALF;

#pragma unroll
        for (int u = 0; u < 2; u++) {               // warp's 2 k16-chunks per BK=128
            const int kk = wid * 2 + u;
            const uint32_t ca = (uint32_t)(kk * 2) + a_hi;
            const uint32_t cb = (uint32_t)(kk * 2) + b_hi;
            uint32_t a[4][4];
#pragma unroll
            for (int i = 0; i < 4; i++)
                ldsm4(a[i][0], a[i][1], a[i][2], a[i][3],
                      sA + a_off[i] + ((ca ^ a_xor[i]) << 4));
            uint32_t bf[8][2];
#pragma unroll
            for (int g = 0; g < 4; g++) {
                uint32_t r0, r1, r2, r3;
                ldsm4(r0, r1, r2, r3, sB + b_off[g] + ((cb ^ b_xor[g]) << 4));
                bf[g * 2 + 0][0] = r0; bf[g * 2 + 0][1] = r1;
                bf[g * 2 + 1][0] = r2; bf[g * 2 + 1][1] = r3;
            }
#pragma unroll
            for (int i = 0; i < 4; i++)
#pragma unroll
                for (int j = 0; j < 8; j++)
                    mma16816(acc[i][j], a[i], bf[j]);
        }
    }

    // ---- intra-CTA merge of 4 warp k-partials (identical register layouts)
    float* exch = (float*)dynp;                     // dynb-based, 64KB region
    __syncthreads();
#pragma unroll
    for (int i = 0; i < 4; i++)
#pragma unroll
        for (int j = 0; j < 8; j++)
#pragma unroll
            for (int r = 0; r < 4; r++)
                exch[wid * 4096 + (i * 32 + j * 4 + r) * 32 + lane] = acc[i][j][r];
    __syncthreads();

    float x[32];
#pragma unroll
    for (int s = 0; s < 32; s++) {
        int f = tid + s * 128;
        x[s] = exch[f] + exch[4096 + f] + exch[8192 + f] + exch[12288 + f];
    }

    // ---- cluster barrier #1: both ranks done with mainloop + intra-merge
    asm volatile("barrier.cluster.arrive.aligned;" ::: "memory");
    asm volatile("barrier.cluster.wait.aligned;" ::: "memory");

    // staging region (shared address dynb + 64KB; same base for writer & reader)
    const uint32_t stag = dynb + 65536;
    float* stagp = (float*)(dynp + 65536);
    if (rank == 1) {
        uint32_t rem;
        asm("mapa.shared::cluster.u32 %0, %1, %2;" : "=r"(rem) : "r"(stag), "r"(0));
#pragma unroll
        for (int s = 0; s < 32; s++)
            asm volatile("st.shared::cluster.f32 [%0], %1;"
                         :: "r"(rem + (uint32_t)(tid + s * 128) * 4), "f"(x[s]) : "memory");
    }

    // ---- cluster barrier #2: rank1's DSMEM writes visible to rank0
    asm volatile("barrier.cluster.arrive.aligned;" ::: "memory");
    asm volatile("barrier.cluster.wait.aligned;" ::: "memory");

    if (rank == 0) {
        float ss = 0.f;
#pragma unroll
        for (int s = 0; s < 32; s++) {
            float v = x[s] + stagp[tid + s * 128];
            ss += v * v;
        }
#pragma unroll
        for (int o = 16; o > 0; o >>= 1) ss += __shfl_xor_sync(0xffffffffu, ss, o);
        if (lane == 0) red[wid] = ss;
        __syncthreads();
        if (tid == 0) {
            g_part[cid] = w * (red[0] + red[1] + red[2] + red[3]);
            __threadfence();
            unsigned int old = atomicAdd(&g_ctr, 1u);
            s_last = (old == NCLUSTERS - 1) ? 1 : 0;
        }
        __syncthreads();

        if (s_last) {
            float v = __ldcg(&g_part[tid]) + __ldcg(&g_part[tid + 128]);
            if (tid < NCLUSTERS - 256) v += __ldcg(&g_part[tid + 256]);
            fr[tid] = v;
            __syncthreads();
#pragma unroll
            for (int o = 64; o > 0; o >>= 1) {
                if (tid < o) fr[tid] += fr[tid + o];
                __syncthreads();
            }
            if (tid == 0) {
                out[0] = fr[0] * (100.0f / 16777216.0f);   // (1/T^2)/N^2
                g_ctr = 0;                                 // self-reset for graph replay
            }
        }
    }
}

// ---------------------------------------------------------------------------
extern "C" void kernel_launch(void* const* d_in, const int* in_sizes, int n_in,
                              void* d_out, int out_size)
{
    const float* rgb   = (const float*)d_in[0];
    const float* depth = (const float*)d_in[1];
    const float* ir    = (const float*)d_in[2];
    const float* tmat  = (const float*)d_in[3];
    float* out = (float*)d_out;

    cudaFuncSetAttribute(norm_transpose_kernel,
                         cudaFuncAttributeMaxDynamicSharedMemorySize, SMEM_NT);
    cudaFuncSetAttribute(gram_kernel,
                         cudaFuncAttributeMaxDynamicSharedMemorySize, SMEM_GRAM);

    dim3 ntgrid(N_ROWS / 32, 4);
    norm_transpose_kernel<<<ntgrid, 256, SMEM_NT>>>(rgb, depth, ir, tmat);

    gram_kernel<<<2 * NCLUSTERS, 128, SMEM_GRAM>>>(out);
}

// round 11
// speedup vs baseline: 1.0221x; 1.0221x over previous
#include <cuda_runtime.h>
#include <cuda_fp16.h>
#include <cstdint>

#define N_ROWS 4096
#define DIM    512
#define BK 128
#define K_ITERS (N_ROWS / BK)            // 32
#define ROW_BYTES 256                    // BK=128 fp16
#define A_TILE (64 * ROW_BYTES)          // 16KB
#define B_TILE (32 * ROW_BYTES)          // 8KB
#define STAGE_BYTES (A_TILE + B_TILE)    // 24KB
#define STAGES 3
#define SMEM_GRAM (STAGES * STAGE_BYTES + 1024)   // 74752
#define SMEM_NT   (32 * 513 * 4)

#define NUNITS 672

// Scratch: transposed normalized fp16: [mat][d][k], k contiguous
static __device__ __half g_normT[4][DIM][N_ROWS];
static __device__ float g_part[NUNITS];
static __device__ unsigned int g_ctr;    // zero-init; self-reset by last block

__constant__ int   c_symmat[4] = {3, 0, 1, 2};
__constant__ float c_symw[4]   = {3.f, 1.f, 1.f, 1.f};
// upper-triangle enumeration of 8x8 64-row x 64-col blocks (36 blocks)
__constant__ signed char c_bi36[36] = {0,0,0,0,0,0,0,0, 1,1,1,1,1,1,1, 2,2,2,2,2,2,
                                       3,3,3,3,3, 4,4,4,4, 5,5,5, 6,6, 7};
__constant__ signed char c_bj36[36] = {0,1,2,3,4,5,6,7, 1,2,3,4,5,6,7, 2,3,4,5,6,7,
                                       3,4,5,6,7, 4,5,6,7, 5,6,7, 6,7, 7};

// ---------------------------------------------------------------------------
__device__ __forceinline__ uint32_t s2u(const void* p) {
    uint32_t a;
    asm("{ .reg .u64 t; cvta.to.shared.u64 t, %1; cvt.u32.u64 %0, t; }"
        : "=r"(a) : "l"(p));
    return a;
}
__device__ __forceinline__ void cpasync16(uint32_t dst, const void* src) {
    asm volatile("cp.async.cg.shared.global [%0], [%1], 16;" :: "r"(dst), "l"(src) : "memory");
}
__device__ __forceinline__ void ldsm4(uint32_t& r0, uint32_t& r1, uint32_t& r2,
                                      uint32_t& r3, uint32_t addr) {
    asm volatile("ldmatrix.sync.aligned.m8n8.x4.shared.b16 {%0,%1,%2,%3}, [%4];"
                 : "=r"(r0), "=r"(r1), "=r"(r2), "=r"(r3) : "r"(addr));
}
// f16 x f16 -> f16 accumulate (2 b32 regs = 4 halves)
__device__ __forceinline__ void mma16816_f16(uint32_t* c, const uint32_t* a,
                                             const uint32_t* b) {
    asm volatile(
        "mma.sync.aligned.m16n8k16.row.col.f16.f16.f16.f16 "
        "{%0,%1}, {%2,%3,%4,%5}, {%6,%7}, {%0,%1};"
        : "+r"(c[0]), "+r"(c[1])
        : "r"(a[0]), "r"(a[1]), "r"(a[2]), "r"(a[3]), "r"(b[0]), "r"(b[1]));
}

// ---------------------------------------------------------------------------
// K1: fused per-row L2 norm + normalize + transpose + fp16 cast.
// ---------------------------------------------------------------------------
__global__ __launch_bounds__(256) void norm_transpose_kernel(
    const float* __restrict__ in0, const float* __restrict__ in1,
    const float* __restrict__ in2, const float* __restrict__ in3)
{
    extern __shared__ float tl[];        // [32][513]
    __shared__ float sinv[32];
    const int mat = blockIdx.y;
    const int kc  = blockIdx.x;          // 0..127
    const float* src = (mat == 0) ? in0 : (mat == 1) ? in1 : (mat == 2) ? in2 : in3;
    const int t = threadIdx.x, lane = t & 31, wid = t >> 5;

    const float4* src4 = (const float4*)(src + (size_t)kc * 32 * DIM);
#pragma unroll
    for (int i = 0; i < 16; i++) {
        int idx = t + i * 256;
        int r = idx >> 7, c4 = idx & 127;
        float4 v = src4[idx];
        float* d = &tl[r * 513 + c4 * 4];
        d[0] = v.x; d[1] = v.y; d[2] = v.z; d[3] = v.w;
    }
    __syncthreads();

#pragma unroll
    for (int rr = 0; rr < 4; rr++) {
        int r = wid * 4 + rr;
        float ss = 0.f;
#pragma unroll
        for (int j = 0; j < 16; j++) {
            float v = tl[r * 513 + lane + j * 32];
            ss += v * v;
        }
#pragma unroll
        for (int o = 16; o > 0; o >>= 1) ss += __shfl_xor_sync(0xffffffffu, ss, o);
        if (lane == 0) sinv[r] = rsqrtf(fmaxf(ss, 1e-24f));   // 1/max(||x||,1e-12)
    }
    __syncthreads();

#pragma unroll
    for (int h = 0; h < 2; h++) {
        int d = t + h * 256;
        union { uint32_t u[16]; uint4 v[4]; } pk;
#pragma unroll
        for (int k2 = 0; k2 < 16; k2++) {
            float f0 = tl[(2 * k2    ) * 513 + d] * sinv[2 * k2];
            float f1 = tl[(2 * k2 + 1) * 513 + d] * sinv[2 * k2 + 1];
            __half2 h2 = __floats2half2_rn(f0, f1);
            pk.u[k2] = *(uint32_t*)&h2;
        }
        uint4* dst = (uint4*)&g_normT[mat][d][kc * 32];
#pragma unroll
        for (int q = 0; q < 4; q++) dst[q] = pk.v[q];
    }
}

// ---------------------------------------------------------------------------
// K2: 672 units, each 64x32 x full K=4096. 128 threads = 4 warps; warp w does
// k16-chunks {2w,2w+1} of each BK=128 slab. f16-accumulate mma, promoted to an
// fp32 register shadow every 4 iters (512 k). k-partials merged via smem,
// fused weighted ||C||_F^2 + last-block final reduction.
// ---------------------------------------------------------------------------
__global__ __launch_bounds__(128, 3) void gram_kernel(float* __restrict__ out)
{
    extern __shared__ char dyn[];
    __shared__ float red[4];
    __shared__ float fr[128];
    __shared__ int s_last;

    // ---- decode unit
    const int bid = blockIdx.x;
    int matL, matR, m0, n0; float w;
    if (bid < 288) {
        int p = bid / 72, r = bid % 72;
        int blk = r >> 1, half = r & 1;
        int bi = c_bi36[blk], bj = c_bj36[blk];
        matL = matR = c_symmat[p];
        m0 = bi * 64;
        n0 = bj * 64 + half * 32;
        w = c_symw[p] * ((bi == bj) ? 1.f : 2.f);
    } else {
        int q = bid - 288;
        matL = 3; matR = q >> 7;
        int r = q & 127;
        m0 = (r >> 4) * 64;
        n0 = (r & 15) * 32;
        w = -2.f;
    }
    const char* __restrict__ Ab = (const char*)&g_normT[matL][0][0];
    const char* __restrict__ Bb = (const char*)&g_normT[matR][0][0];

    const int tid  = threadIdx.x;
    const int lane = tid & 31;
    const int wid  = tid >> 5;
    const uint32_t dyn_sa = s2u(dyn);
    const uint32_t dynb = (dyn_sa + 1023) & ~1023u;
    char* dynp = dyn + (dynb - dyn_sa);      // generic ptr aliasing shared addr dynb

    // ---- cp.async: 1536 16B chunks per stage (A 64 rows, B 32 rows), 12/thread
    auto issue_loads = [&](int it) {
        uint32_t sbase = dynb + (uint32_t)(it % STAGES) * STAGE_BYTES;
#pragma unroll
        for (int q = 0; q < 12; q++) {
            int c   = tid + q * 128;             // 0..1535
            int isB = (c >= 1024);
            int row = isB ? ((c - 1024) >> 4) : (c >> 4);
            int q16 = c & 15;
            uint32_t sw = (uint32_t)row * ROW_BYTES + (uint32_t)((q16 ^ (row & 7)) << 4);
            const char* g = (isB ? Bb : Ab)
                          + ((size_t)((isB ? n0 : m0) + row) << 13)   // d-row * 8192B
                          + (size_t)it * ROW_BYTES + q16 * 16;
            cpasync16(sbase + (isB ? A_TILE : 0) + sw, g);
        }
        asm volatile("cp.async.commit_group;" ::: "memory");
    };

    // ---- ldmatrix addressing
    uint32_t a_off[4], a_xor[4];
#pragma unroll
    for (int i = 0; i < 4; i++) {
        int row = i * 16 + (lane & 15);
        a_off[i] = (uint32_t)row * ROW_BYTES;
        a_xor[i] = (uint32_t)(row & 7);
    }
    const uint32_t a_hi = (uint32_t)(lane >> 4);
    uint32_t b_off[2], b_xor[2];
#pragma unroll
    for (int g = 0; g < 2; g++) {
        int row = g * 16 + ((lane >> 4) & 1) * 8 + (lane & 7);
        b_off[g] = (uint32_t)row * ROW_BYTES;
        b_xor[g] = (uint32_t)(row & 7);
    }
    const uint32_t b_hi = (uint32_t)((lane >> 3) & 1);

    float acc[4][4][4];                  // fp32 shadow
    uint32_t cf[4][4][2];                // f16 working accumulators
#pragma unroll
    for (int i = 0; i < 4; i++)
#pragma unroll
        for (int j = 0; j < 4; j++) {
#pragma unroll
            for (int r = 0; r < 4; r++) acc[i][j][r] = 0.f;
            cf[i][j][0] = 0u; cf[i][j][1] = 0u;
        }

    issue_loads(0);
    issue_loads(1);

    for (int it = 0; it < K_ITERS; ++it) {
        if (it < K_ITERS - 1)
            asm volatile("cp.async.wait_group 1;" ::: "memory");
        else
            asm volatile("cp.async.wait_group 0;" ::: "memory");
        __syncthreads();

        const int nx = it + 2;
        if (nx < K_ITERS) issue_loads(nx);

        const uint32_t sA = dynb + (uint32_t)(it % STAGES) * STAGE_BYTES;
        const uint32_t sB = sA + A_TILE;

#pragma unroll
        for (int u = 0; u < 2; u++) {            // warp's 2 k16-chunks per BK=128
            const int kk = wid * 2 + u;
            const uint32_t ca = (uint32_t)(kk * 2) + a_hi;
            const uint32_t cb = (uint32_t)(kk * 2) + b_hi;
            uint32_t a[4][4];
#pragma unroll
            for (int i = 0; i < 4; i++)
                ldsm4(a[i][0], a[i][1], a[i][2], a[i][3],
                      sA + a_off[i] + ((ca ^ a_xor[i]) << 4));
            uint32_t bf[4][2];
#pragma unroll
            for (int g = 0; g < 2; g++) {
                uint32_t r0, r1, r2, r3;
                ldsm4(r0, r1, r2, r3, sB + b_off[g] + ((cb ^ b_xor[g]) << 4));
                bf[g * 2 + 0][0] = r0; bf[g * 2 + 0][1] = r1;
                bf[g * 2 + 1][0] = r2; bf[g * 2 + 1][1] = r3;
            }
#pragma unroll
            for (int i = 0; i < 4; i++)
#pragma unroll
                for (int j = 0; j < 4; j++)
                    mma16816_f16(cf[i][j], a[i], bf[j]);
        }

        // ---- segment promotion: every 4 iters (512 k) fold f16 into fp32
        if ((it & 3) == 3) {
#pragma unroll
            for (int i = 0; i < 4; i++)
#pragma unroll
                for (int j = 0; j < 4; j++) {
                    float2 f0 = __half22float2(*(__half2*)&cf[i][j][0]);
                    float2 f1 = __half22float2(*(__half2*)&cf[i][j][1]);
                    acc[i][j][0] += f0.x; acc[i][j][1] += f0.y;
                    acc[i][j][2] += f1.x; acc[i][j][3] += f1.y;
                    cf[i][j][0] = 0u; cf[i][j][1] = 0u;
                }
        }
    }

    // ---- merge 4 warp k-partials via smem (identical register layouts)
    float* exch = (float*)dynp;          // 32KB needed, stage region is dead
    __syncthreads();
#pragma unroll
    for (int i = 0; i < 4; i++)
#pragma unroll
        for (int j = 0; j < 4; j++)
#pragma unroll
            for (int r = 0; r < 4; r++)
                exch[wid * 2048 + (i * 16 + j * 4 + r) * 32 + lane] = acc[i][j][r];
    __syncthreads();

    float ss = 0.f;
#pragma unroll
    for (int s = 0; s < 16; s++) {
        int f = tid + s * 128;
        float x = exch[f] + exch[2048 + f] + exch[4096 + f] + exch[6144 + f];
        ss += x * x;
    }
#pragma unroll
    for (int o = 16; o > 0; o >>= 1) ss += __shfl_xor_sync(0xffffffffu, ss, o);
    if (lane == 0) red[wid] = ss;
    __syncthreads();
    if (tid == 0) {
        g_part[bid] = w * (red[0] + red[1] + red[2] + red[3]);
        __threadfence();
        unsigned int old = atomicAdd(&g_ctr, 1u);
        s_last = (old == NUNITS - 1) ? 1 : 0;
    }
    __syncthreads();

    // last finished block: deterministic fixed-order final reduction
    if (s_last) {
        float v = 0.f;
#pragma unroll
        for (int k = 0; k < 6; k++) {            // 672 = 5*128 + 32
            int idx = tid + k * 128;
            if (idx < NUNITS) v += __ldcg(&g_part[idx]);
        }
        fr[tid] = v;
        __syncthreads();
#pragma unroll
        for (int o = 64; o > 0; o >>= 1) {
            if (tid < o) fr[tid] += fr[tid + o];
            __syncthreads();
        }
        if (tid == 0) {
            out[0] = fr[0] * (100.0f / 16777216.0f);   // (1/T^2)/N^2
            g_ctr = 0;                                 // self-reset for graph replay
        }
    }
}

// ---------------------------------------------------------------------------
extern "C" void kernel_launch(void* const* d_in, const int* in_sizes, int n_in,
                              void* d_out, int out_size)
{
    const float* rgb   = (const float*)d_in[0];
    const float* depth = (const float*)d_in[1];
    const float* ir    = (const float*)d_in[2];
    const float* tmat  = (const float*)d_in[3];
    float* out = (float*)d_out;

    cudaFuncSetAttribute(norm_transpose_kernel,
                         cudaFuncAttributeMaxDynamicSharedMemorySize, SMEM_NT);
    cudaFuncSetAttribute(gram_kernel,
                         cudaFuncAttributeMaxDynamicSharedMemorySize, SMEM_GRAM);

    dim3 ntgrid(N_ROWS / 32, 4);
    norm_transpose_kernel<<<ntgrid, 256, SMEM_NT>>>(rgb, depth, ir, tmat);

    gram_kernel<<<NUNITS, 128, SMEM_GRAM>>>(out);
}

// round 13
// speedup vs baseline: 1.4046x; 1.3742x over previous
#include <cuda_runtime.h>
#include <cuda_fp16.h>
#include <cstdint>

#define N_ROWS 4096
#define DIM    512
#define BK 128
#define K_ITERS (N_ROWS / BK)            // 32
#define A_TILE (128 * 128)               // 16KB: 128 k-rows x 128B (64 m-cols)
#define B_TILE (64 * 128)                // 8KB: 128 k-rows packed 2/row (32 n-cols)
#define STAGE_BYTES (A_TILE + B_TILE)    // 24KB
#define STAGES 3
#define SMEM_GRAM (STAGES * STAGE_BYTES + 1024)   // 74752

#define NUNITS 672

// Scratch: normalized fp16, SAME layout as input: [mat][n][d]
static __device__ __half g_normH[4][N_ROWS][DIM];
static __device__ float g_part[NUNITS];
static __device__ unsigned int g_ctr;    // zero-init; self-reset by last block

__constant__ int   c_symmat[4] = {3, 0, 1, 2};
__constant__ float c_symw[4]   = {3.f, 1.f, 1.f, 1.f};
// upper-triangle enumeration of 8x8 blocks of 64x64 (36 blocks)
__constant__ signed char c_bi36[36] = {0,0,0,0,0,0,0,0, 1,1,1,1,1,1,1, 2,2,2,2,2,2,
                                       3,3,3,3,3, 4,4,4,4, 5,5,5, 6,6, 7};
__constant__ signed char c_bj36[36] = {0,1,2,3,4,5,6,7, 1,2,3,4,5,6,7, 2,3,4,5,6,7,
                                       3,4,5,6,7, 4,5,6,7, 5,6,7, 6,7, 7};

// ---------------------------------------------------------------------------
__device__ __forceinline__ uint32_t s2u(const void* p) {
    uint32_t a;
    asm("{ .reg .u64 t; cvta.to.shared.u64 t, %1; cvt.u32.u64 %0, t; }"
        : "=r"(a) : "l"(p));
    return a;
}
__device__ __forceinline__ void cpasync16(uint32_t dst, const void* src) {
    asm volatile("cp.async.cg.shared.global [%0], [%1], 16;" :: "r"(dst), "l"(src) : "memory");
}
__device__ __forceinline__ void ldsm4t(uint32_t& r0, uint32_t& r1, uint32_t& r2,
                                       uint32_t& r3, uint32_t addr) {
    asm volatile("ldmatrix.sync.aligned.m8n8.x4.trans.shared.b16 {%0,%1,%2,%3}, [%4];"
                 : "=r"(r0), "=r"(r1), "=r"(r2), "=r"(r3) : "r"(addr));
}
// f16 x f16 -> f16 accumulate
__device__ __forceinline__ void mma16816_f16(uint32_t* c, const uint32_t* a,
                                             const uint32_t* b) {
    asm volatile(
        "mma.sync.aligned.m16n8k16.row.col.f16.f16.f16.f16 "
        "{%0,%1}, {%2,%3,%4,%5}, {%6,%7}, {%0,%1};"
        : "+r"(c[0]), "+r"(c[1])
        : "r"(a[0]), "r"(a[1]), "r"(a[2]), "r"(a[3]), "r"(b[0]), "r"(b[1]));
}

// ---------------------------------------------------------------------------
// K1: streaming per-row L2 normalize, fp32 [N,D] -> fp16 [N,D]. Warp per row.
// ---------------------------------------------------------------------------
__global__ __launch_bounds__(256) void norm_kernel(
    const float* __restrict__ in0, const float* __restrict__ in1,
    const float* __restrict__ in2, const float* __restrict__ in3)
{
    const int row  = blockIdx.x * 8 + (threadIdx.x >> 5);   // 0..16383
    const int lane = threadIdx.x & 31;
    const int mat  = row >> 12;
    const int r    = row & (N_ROWS - 1);
    const float* src = (mat == 0) ? in0 : (mat == 1) ? in1 : (mat == 2) ? in2 : in3;
    const float4* s4 = (const float4*)(src + (size_t)r * DIM);

    float4 v[4];
    float ss = 0.f;
#pragma unroll
    for (int j = 0; j < 4; j++) {
        v[j] = s4[lane + j * 32];
        ss += v[j].x * v[j].x + v[j].y * v[j].y + v[j].z * v[j].z + v[j].w * v[j].w;
    }
#pragma unroll
    for (int o = 16; o > 0; o >>= 1) ss += __shfl_xor_sync(0xffffffffu, ss, o);
    const float inv = rsqrtf(fmaxf(ss, 1e-24f));   // 1/max(||x||,1e-12)

    uint2* dst = (uint2*)&g_normH[mat][r][0];      // 8B per float4 chunk
#pragma unroll
    for (int j = 0; j < 4; j++) {
        __half2 h0 = __floats2half2_rn(v[j].x * inv, v[j].y * inv);
        __half2 h1 = __floats2half2_rn(v[j].z * inv, v[j].w * inv);
        uint2 pk = make_uint2(*(uint32_t*)&h0, *(uint32_t*)&h1);
        dst[lane + j * 32] = pk;
    }
}

// ---------------------------------------------------------------------------
// K2: 672 units, each 64x32 x full K=4096. 128 threads = 4 warps; warp w owns
// k-rows [32w,32w+32) of each BK=128 slab: loads them itself (per-warp
// cp.async groups) and computes with ldmatrix.trans -> NO block barrier in the
// mainloop. f16 accumulate, fp32 promotion every 4 iters. k-partials merged
// via smem at the end; fused weighted ||C||_F^2 + last-block reduction.
// smem per stage: A 128 k-rows x 128B (m-cols), B 128 k-rows packed 2-per-row.
// ---------------------------------------------------------------------------
__global__ __launch_bounds__(128, 3) void gram_kernel(float* __restrict__ out)
{
    extern __shared__ char dyn[];
    __shared__ float red[4];
    __shared__ float fr[128];
    __shared__ int s_last;

    // ---- decode unit
    const int bid = blockIdx.x;
    int matL, matR, m0, n0; float w;
    if (bid < 288) {
        int p = bid / 72, r = bid % 72;
        int blk = r >> 1, half = r & 1;
        int bi = c_bi36[blk], bj = c_bj36[blk];
        matL = matR = c_symmat[p];
        m0 = bi * 64;
        n0 = bj * 64 + half * 32;
        w = c_symw[p] * ((bi == bj) ? 1.f : 2.f);
    } else {
        int q = bid - 288;
        matL = 3; matR = q >> 7;
        int r = q & 127;
        m0 = (r >> 4) * 64;
        n0 = (r & 15) * 32;
        w = -2.f;
    }
    const char* __restrict__ Ab = (const char*)&g_normH[matL][0][0] + m0 * 2;
    const char* __restrict__ Bb = (const char*)&g_normH[matR][0][0] + n0 * 2;

    const int tid  = threadIdx.x;
    const int lane = tid & 31;
    const int wid  = tid >> 5;
    const int w32  = wid * 32;                   // this warp's k-row base in slab
    const uint32_t dyn_sa = s2u(dyn);
    const uint32_t dynb = (dyn_sa + 1023) & ~1023u;
    char* dynp = dyn + (dynb - dyn_sa);

    // ---- per-warp loads: A 256 chunks (8/lane), B 128 chunks (4/lane)
    auto issue_loads = [&](int it) {
        const uint32_t sbase = dynb + (uint32_t)(it % STAGES) * STAGE_BYTES;
        const size_t gk = (size_t)(it * BK + w32) * (DIM * 2);   // k-row byte base
#pragma unroll
        for (int q = 0; q < 8; q++) {            // A
            int id = lane + q * 32;              // 0..255
            int rl = id >> 3, c = id & 7;        // local k-row, 16B chunk
            int kr = w32 + rl;
            uint32_t sw = (uint32_t)kr * 128 + (uint32_t)((c ^ (kr & 7)) << 4);
            cpasync16(sbase + sw, Ab + gk + (size_t)rl * (DIM * 2) + c * 16);
        }
#pragma unroll
        for (int q = 0; q < 4; q++) {            // B (rows packed 2-per-128B)
            int id = lane + q * 32;              // 0..127
            int rl = id >> 2, c = id & 3;
            int kr = w32 + rl;
            int srow = kr >> 1;
            uint32_t cc = (uint32_t)(((kr & 1) << 2) | c);
            uint32_t sw = (uint32_t)srow * 128 + ((cc ^ (srow & 7)) << 4);
            cpasync16(sbase + A_TILE + sw, Bb + gk + (size_t)rl * (DIM * 2) + c * 16);
        }
        asm volatile("cp.async.commit_group;" ::: "memory");
    };

    // ---- ldmatrix.trans addressing (per u = k16-half of this warp's 32 rows)
    const int g8 = lane >> 3, i8 = lane & 7;
    uint32_t aRow[2], aXor[2], bRow[2], bXor[2], bHi4[2];
#pragma unroll
    for (int u = 0; u < 2; u++) {
        int ka = w32 + u * 16 + ((g8 >> 1) & 1) * 8 + i8;   // A: k+8 on g bit1
        aRow[u] = (uint32_t)ka * 128;
        aXor[u] = (uint32_t)(ka & 7);
        int kb = w32 + u * 16 + (g8 & 1) * 8 + i8;          // B: k+8 on g bit0
        bRow[u] = (uint32_t)(kb >> 1) * 128;
        bXor[u] = (uint32_t)((kb >> 1) & 7);
        bHi4[u] = (uint32_t)((kb & 1) << 2);
    }
    const uint32_t aC = (uint32_t)(g8 & 1);        // A: m+8 on g bit0
    const uint32_t bC = (uint32_t)((g8 >> 1) & 1); // B: n+8 on g bit1

    float acc[4][4][4];
    uint32_t cf[4][4][2];
#pragma unroll
    for (int i = 0; i < 4; i++)
#pragma unroll
        for (int j = 0; j < 4; j++) {
#pragma unroll
            for (int r = 0; r < 4; r++) acc[i][j][r] = 0.f;
            cf[i][j][0] = 0u; cf[i][j][1] = 0u;
        }

    issue_loads(0);
    issue_loads(1);

    for (int it = 0; it < K_ITERS; ++it) {
        if (it < K_ITERS - 1)
            asm volatile("cp.async.wait_group 1;" ::: "memory");
        else
            asm volatile("cp.async.wait_group 0;" ::: "memory");
        __syncwarp();                            // per-warp pipeline: no CTA barrier

        const int nx = it + 2;
        if (nx < K_ITERS) issue_loads(nx);

        const uint32_t sA = dynb + (uint32_t)(it % STAGES) * STAGE_BYTES;
        const uint32_t sB = sA + A_TILE;

#pragma unroll
        for (int u = 0; u < 2; u++) {
            uint32_t a[4][4];
#pragma unroll
            for (int i = 0; i < 4; i++) {
                uint32_t c = (uint32_t)(i * 2) + aC;
                ldsm4t(a[i][0], a[i][1], a[i][2], a[i][3],
                       sA + aRow[u] + ((c ^ aXor[u]) << 4));
            }
            uint32_t bf[4][2];
#pragma unroll
            for (int j = 0; j < 2; j++) {
                uint32_t cc = bHi4[u] | ((uint32_t)(j * 2) + bC);
                uint32_t r0, r1, r2, r3;
                ldsm4t(r0, r1, r2, r3, sB + bRow[u] + ((cc ^ bXor[u]) << 4));
                bf[j * 2 + 0][0] = r0; bf[j * 2 + 0][1] = r1;
                bf[j * 2 + 1][0] = r2; bf[j * 2 + 1][1] = r3;
            }
#pragma unroll
            for (int i = 0; i < 4; i++)
#pragma unroll
                for (int j = 0; j < 4; j++)
                    mma16816_f16(cf[i][j], a[i], bf[j]);
        }

        if ((it & 3) == 3) {                     // promote f16 -> fp32 every 512 k
#pragma unroll
            for (int i = 0; i < 4; i++)
#pragma unroll
                for (int j = 0; j < 4; j++) {
                    float2 f0 = __half22float2(*(__half2*)&cf[i][j][0]);
                    float2 f1 = __half22float2(*(__half2*)&cf[i][j][1]);
                    acc[i][j][0] += f0.x; acc[i][j][1] += f0.y;
                    acc[i][j][2] += f1.x; acc[i][j][3] += f1.y;
                    cf[i][j][0] = 0u; cf[i][j][1] = 0u;
                }
        }
    }

    // ---- merge 4 warp k-partials via smem (identical register layouts)
    float* exch = (float*)dynp;
    __syncthreads();                             // all warps done with their stages
#pragma unroll
    for (int i = 0; i < 4; i++)
#pragma unroll
        for (int j = 0; j < 4; j++)
#pragma unroll
            for (int r = 0; r < 4; r++)
                exch[wid * 2048 + (i * 16 + j * 4 + r) * 32 + lane] = acc[i][j][r];
    __syncthreads();

    float ss = 0.f;
#pragma unroll
    for (int s = 0; s < 16; s++) {
        int f = tid + s * 128;
        float x = exch[f] + exch[2048 + f] + exch[4096 + f] + exch[6144 + f];
        ss += x * x;
    }
#pragma unroll
    for (int o = 16; o > 0; o >>= 1) ss += __shfl_xor_sync(0xffffffffu, ss, o);
    if (lane == 0) red[wid] = ss;
    __syncthreads();
    if (tid == 0) {
        g_part[bid] = w * (red[0] + red[1] + red[2] + red[3]);
        __threadfence();
        unsigned int old = atomicAdd(&g_ctr, 1u);
        s_last = (old == NUNITS - 1) ? 1 : 0;
    }
    __syncthreads();

    if (s_last) {
        float v = 0.f;
#pragma unroll
        for (int k = 0; k < 6; k++) {            // 672 = 5*128 + 32
            int idx = tid + k * 128;
            if (idx < NUNITS) v += __ldcg(&g_part[idx]);
        }
        fr[tid] = v;
        __syncthreads();
#pragma unroll
        for (int o = 64; o > 0; o >>= 1) {
            if (tid < o) fr[tid] += fr[tid + o];
            __syncthreads();
        }
        if (tid == 0) {
            out[0] = fr[0] * (100.0f / 16777216.0f);   // (1/T^2)/N^2
            g_ctr = 0;                                 // self-reset for graph replay
        }
    }
}

// ---------------------------------------------------------------------------
extern "C" void kernel_launch(void* const* d_in, const int* in_sizes, int n_in,
                              void* d_out, int out_size)
{
    const float* rgb   = (const float*)d_in[0];
    const float* depth = (const float*)d_in[1];
    const float* ir    = (const float*)d_in[2];
    const float* tmat  = (const float*)d_in[3];
    float* out = (float*)d_out;

    cudaFuncSetAttribute(gram_kernel,
                         cudaFuncAttributeMaxDynamicSharedMemorySize, SMEM_GRAM);

    norm_kernel<<<2048, 256>>>(rgb, depth, ir, tmat);
    gram_kernel<<<NUNITS, 128, SMEM_GRAM>>>(out);
}